// round 15
// baseline (speedup 1.0000x reference)
#include <cuda_runtime.h>
#include <cuda_fp16.h>
#include <cstdint>

#define NN 50000
#define EE 500000
#define DD 384
#define BB 64
#define HMAX 6
#define ETOT (EE + NN)
#define MAXDEG 512

// ---------------- scratch (static device allocations) ----------------
__device__ __align__(16) __half g_h[(size_t)NN * DD];   // projected features (fp16)
__device__ __align__(16) float g_out[(size_t)NN * DD];  // layer-3 aggregated output
__device__ __align__(16) float g_x[(size_t)NN * DD];    // layer input (x1, x2), tf32-rounded
__device__ __align__(16) float g_Wr[3 * DD * DD];       // tf32-rounded weights
__device__ float g_ssrc[3 * NN * HMAX];                 // per-layer slabs
__device__ float g_sdst[3 * NN * HMAX];
__device__ int g_deg[NN];
__device__ int g_cur[NN];
__device__ int g_csr_off[NN + 1];
__device__ int g_csr_src[ETOT];
__device__ int g_off[BB + 2];

// ================= helpers =================
__device__ __forceinline__ uint32_t smem_u32(const void* p) {
    uint32_t a;
    asm("{ .reg .u64 t; cvta.to.shared.u64 t, %1; cvt.u32.u64 %0, t; }" : "=r"(a) : "l"(p));
    return a;
}
#define CP16(sa, g) asm volatile("cp.async.cg.shared.global [%0], [%1], 16;" ::"r"(sa), "l"(g))
#define CP_COMMIT() asm volatile("cp.async.commit_group;" ::: "memory")

__device__ __forceinline__ uint32_t to_tf32(float x) {
    uint32_t u;
    asm("cvt.rna.tf32.f32 %0, %1;" : "=r"(u) : "f"(x));
    return u;
}
__device__ __forceinline__ float tf32f(float x) { return __uint_as_float(to_tf32(x)); }

__device__ __forceinline__ void mma_tf32(float* d, uint32_t a0, uint32_t a1, uint32_t a2,
                                         uint32_t a3, uint32_t b0, uint32_t b1) {
    asm volatile(
        "mma.sync.aligned.m16n8k8.row.col.f32.tf32.tf32.f32 "
        "{%0,%1,%2,%3}, {%4,%5,%6,%7}, {%8,%9}, {%0,%1,%2,%3};"
        : "+f"(d[0]), "+f"(d[1]), "+f"(d[2]), "+f"(d[3])
        : "r"(a0), "r"(a1), "r"(a2), "r"(a3), "r"(b0), "r"(b1));
}

// ================= weight pre-round: W1 + layer-1 logit zeroing (critical path) =================
__global__ void round_w1(const float* __restrict__ W1, float* __restrict__ z0,
                         float* __restrict__ z1) {
    int i4 = blockIdx.x * blockDim.x + threadIdx.x;
    const int NW = DD * DD / 4;
    if (i4 < NW) {
        float4 v = ((const float4*)W1)[i4];
        v.x = tf32f(v.x);
        v.y = tf32f(v.y);
        v.z = tf32f(v.z);
        v.w = tf32f(v.w);
        ((float4*)g_Wr)[i4] = v;
    }
    for (int i = i4; i < NN; i += gridDim.x * blockDim.x) {
        ((float4*)z0)[i] = make_float4(0.f, 0.f, 0.f, 0.f);
        ((float4*)z1)[i] = make_float4(0.f, 0.f, 0.f, 0.f);
    }
}

// ================= weight pre-round: W2 + W3 (aux stream) =================
__global__ void round_w23(const float* __restrict__ W2, const float* __restrict__ W3) {
    int i4 = blockIdx.x * blockDim.x + threadIdx.x;
    const int NW = DD * DD / 4;
    if (i4 >= 2 * NW) return;
    const float4* src = (i4 < NW) ? (const float4*)W2 : (const float4*)W3;
    int o = (i4 < NW) ? i4 : i4 - NW;
    float4 v = src[o];
    v.x = tf32f(v.x);
    v.y = tf32f(v.y);
    v.z = tf32f(v.z);
    v.w = tf32f(v.w);
    ((float4*)g_Wr)[NW + i4] = v;
}

// ================= tf32 mma.sync GEMM + fused attention logits =================
#define ST_FLOATS (4608 + 4352)
#define GEMM_SMEM (2 * ST_FLOATS * 4)

template <int H, int C, bool CVTA>
__global__ __launch_bounds__(256, 2) void gemm_mma(const float* __restrict__ A,
                                                   const float* __restrict__ W,
                                                   const float* __restrict__ asrc,
                                                   const float* __restrict__ adst,
                                                   float* __restrict__ ssrc,
                                                   float* __restrict__ sdst) {
    extern __shared__ float sm[];
    int tid = threadIdx.x;
    int m0 = blockIdx.y * 128, n0 = blockIdx.x * 128;
    int lane = tid & 31, wid = tid >> 5;
    int wm = wid & 3, wn = wid >> 2;
    int r = lane >> 2, kq = lane & 3;

    float acc[2][8][4];
#pragma unroll
    for (int i = 0; i < 2; i++)
#pragma unroll
        for (int j = 0; j < 8; j++)
#pragma unroll
            for (int q = 0; q < 4; q++) acc[i][j][q] = 0.f;

    auto issue = [&](int c, int st) {
        float* As = sm + st * ST_FLOATS;
        float* Bs = As + 4608;
        int k0 = c * 32;
#pragma unroll
        for (int i = 0; i < 4; i++) {
            int idx = i * 256 + tid;
            int m = idx >> 3, seg = idx & 7;
            int row = m0 + m;
            if (row > NN - 1) row = NN - 1;
            CP16(smem_u32(As + m * 36 + seg * 4), A + (size_t)row * DD + k0 + seg * 4);
        }
#pragma unroll
        for (int i = 0; i < 4; i++) {
            int idx = i * 256 + tid;
            int kr = idx >> 5, seg = idx & 31;
            CP16(smem_u32(Bs + kr * 136 + seg * 4), W + (size_t)(k0 + kr) * DD + n0 + seg * 4);
        }
        CP_COMMIT();
    };

    issue(0, 0);
    for (int c = 0; c < 12; c++) {
        int st = c & 1;
        if (c < 11) {
            issue(c + 1, st ^ 1);
            asm volatile("cp.async.wait_group 1;" ::: "memory");
        } else {
            asm volatile("cp.async.wait_group 0;" ::: "memory");
        }
        __syncthreads();
        const float* As = sm + st * ST_FLOATS;
        const float* Bs = As + 4608;
#pragma unroll
        for (int ks = 0; ks < 4; ks++) {
            int kk = ks * 8;
            uint32_t a[2][4], b[8][2];
#pragma unroll
            for (int mi = 0; mi < 2; mi++) {
                int row = wm * 32 + mi * 16 + r;
                if (CVTA) {
                    a[mi][0] = to_tf32(As[row * 36 + kk + kq]);
                    a[mi][1] = to_tf32(As[(row + 8) * 36 + kk + kq]);
                    a[mi][2] = to_tf32(As[row * 36 + kk + kq + 4]);
                    a[mi][3] = to_tf32(As[(row + 8) * 36 + kk + kq + 4]);
                } else {
                    a[mi][0] = __float_as_uint(As[row * 36 + kk + kq]);
                    a[mi][1] = __float_as_uint(As[(row + 8) * 36 + kk + kq]);
                    a[mi][2] = __float_as_uint(As[row * 36 + kk + kq + 4]);
                    a[mi][3] = __float_as_uint(As[(row + 8) * 36 + kk + kq + 4]);
                }
            }
#pragma unroll
            for (int j = 0; j < 8; j++) {
                int col = wn * 64 + j * 8 + r;
                b[j][0] = __float_as_uint(Bs[(kk + kq) * 136 + col]);
                b[j][1] = __float_as_uint(Bs[(kk + kq + 4) * 136 + col]);
            }
#pragma unroll
            for (int mi = 0; mi < 2; mi++)
#pragma unroll
                for (int j = 0; j < 8; j++)
                    mma_tf32(acc[mi][j], a[mi][0], a[mi][1], a[mi][2], a[mi][3], b[j][0], b[j][1]);
        }
        __syncthreads();
    }

    // ---- store h as fp16 ----
#pragma unroll
    for (int mi = 0; mi < 2; mi++) {
#pragma unroll
        for (int j = 0; j < 8; j++) {
            int row = m0 + wm * 32 + mi * 16 + r;
            int col = n0 + wn * 64 + j * 8 + kq * 2;
            if (row < NN)
                *(__half2*)&g_h[(size_t)row * DD + col] =
                    __floats2half2_rn(acc[mi][j][0], acc[mi][j][1]);
            if (row + 8 < NN)
                *(__half2*)&g_h[(size_t)(row + 8) * DD + col] =
                    __floats2half2_rn(acc[mi][j][2], acc[mi][j][3]);
        }
    }

    // ---- fused attention logits (fp32 accumulators) ----
    int n0base = n0 + wn * 64;
    int hlo = n0base / C;
    int hhi = (n0base + 63) / C;
    float ss[4][2] = {}, sd[4][2] = {};
#pragma unroll
    for (int j = 0; j < 8; j++) {
        int colb = n0base + j * 8 + kq * 2;
        int bkt = (n0base + j * 8) / C - hlo;
#pragma unroll
        for (int q = 0; q < 2; q++) {
            float as = asrc[colb + q], ad = adst[colb + q];
            ss[0][bkt] += acc[0][j][q] * as;
            sd[0][bkt] += acc[0][j][q] * ad;
            ss[1][bkt] += acc[0][j][2 + q] * as;
            sd[1][bkt] += acc[0][j][2 + q] * ad;
            ss[2][bkt] += acc[1][j][q] * as;
            sd[2][bkt] += acc[1][j][q] * ad;
            ss[3][bkt] += acc[1][j][2 + q] * as;
            sd[3][bkt] += acc[1][j][2 + q] * ad;
        }
    }
#pragma unroll
    for (int i = 0; i < 4; i++)
#pragma unroll
        for (int bkt = 0; bkt < 2; bkt++)
#pragma unroll
            for (int o = 1; o < 4; o <<= 1) {
                ss[i][bkt] += __shfl_xor_sync(0xffffffffu, ss[i][bkt], o);
                sd[i][bkt] += __shfl_xor_sync(0xffffffffu, sd[i][bkt], o);
            }
    if (kq == 0) {
        int rows[4] = {m0 + wm * 32 + r, m0 + wm * 32 + r + 8, m0 + wm * 32 + r + 16,
                       m0 + wm * 32 + r + 24};
#pragma unroll
        for (int i = 0; i < 4; i++) {
            if (rows[i] < NN) {
                atomicAdd(&ssrc[rows[i] * H + hlo], ss[i][0]);
                atomicAdd(&sdst[rows[i] * H + hlo], sd[i][0]);
                if (hhi > hlo) {
                    atomicAdd(&ssrc[rows[i] * H + hlo + 1], ss[i][1]);
                    atomicAdd(&sdst[rows[i] * H + hlo + 1], sd[i][1]);
                }
            }
        }
    }
}

// ---------------- CSR build ----------------
__global__ void count_kernel(const int* __restrict__ edst) {
    int e = blockIdx.x * blockDim.x + threadIdx.x;
    if (e >= ETOT) return;
    int d = (e < EE) ? edst[e] : (e - EE);
    atomicAdd(&g_deg[d], 1);
}

__global__ void scan_kernel() {
    const int T = 1024;
    const int CH = (NN + T - 1) / T;
    __shared__ int warp_sums[32];
    int t = threadIdx.x;
    int base = t * CH;
    int s = 0;
    for (int i = 0; i < CH; i++) {
        int idx = base + i;
        if (idx < NN) s += g_deg[idx];
    }
    int lane = t & 31, wid = t >> 5;
    int v = s;
#pragma unroll
    for (int o = 1; o < 32; o <<= 1) {
        int u = __shfl_up_sync(0xffffffffu, v, o);
        if (lane >= o) v += u;
    }
    if (lane == 31) warp_sums[wid] = v;
    __syncthreads();
    if (wid == 0) {
        int w = warp_sums[lane];
#pragma unroll
        for (int o = 1; o < 32; o <<= 1) {
            int u = __shfl_up_sync(0xffffffffu, w, o);
            if (lane >= o) w += u;
        }
        warp_sums[lane] = w;
    }
    __syncthreads();
    int excl = v - s + (wid > 0 ? warp_sums[wid - 1] : 0);
    int run = excl;
    for (int i = 0; i < CH; i++) {
        int idx = base + i;
        if (idx < NN) {
            g_csr_off[idx] = run;
            run += g_deg[idx];
        }
    }
    if (t == 0) g_csr_off[NN] = ETOT;
}

__global__ void fill_kernel(const int* __restrict__ esrc, const int* __restrict__ edst) {
    int e = blockIdx.x * blockDim.x + threadIdx.x;
    if (e >= ETOT) return;
    int s, d;
    if (e < EE) {
        s = esrc[e];
        d = edst[e];
    } else {
        s = d = e - EE;
    }
    int slot = g_csr_off[d] + atomicAdd(&g_cur[d], 1);
    g_csr_src[slot] = s;
}

// ---------------- fused softmax-alpha + gather + (bias+LN+ReLU) ----------------
// 192 threads, 2 channels per thread via __half2 loads.
template <int H, int C, bool DO_LN>
__global__ __launch_bounds__(192) void agg_kernel(const float* __restrict__ b,
                                                  const float* __restrict__ gam,
                                                  const float* __restrict__ bet,
                                                  const float* __restrict__ ssrc,
                                                  const float* __restrict__ sdst) {
    __shared__ float wbuf[MAXDEG * H];
    __shared__ float invd[H];
    __shared__ float red[6], red2[6];
    int d = blockIdx.x;
    int t = threadIdx.x;  // 0..191
    int beg = g_csr_off[d], end = g_csr_off[d + 1];
    int deg = end - beg;
    const int c = 2 * t;      // channel pair (c, c+1); never straddles a head (C even)
    const int h = c / C;
    float a0 = 0.f, a1 = 0.f;

    if (deg <= MAXDEG) {
        int items = deg * H;
        for (int i = t; i < items; i += 192) {
            int p = i / H, hh = i - p * H;
            int s = g_csr_src[beg + p];
            float tt = ssrc[s * H + hh] + sdst[d * H + hh];
            tt = tt > 0.f ? tt : 0.2f * tt;
            wbuf[i] = __expf(tt);
        }
        __syncthreads();
        if (t < H) {
            float dn = 0.f;
            for (int p = 0; p < deg; p++) dn += wbuf[p * H + t];
            invd[t] = 1.f / (dn + 1e-16f);
        }
        __syncthreads();
        for (int i = t; i < items; i += 192) {
            int hh = i - (i / H) * H;
            wbuf[i] *= invd[hh];
        }
        __syncthreads();
        int p = 0;
        for (; p + 4 <= deg; p += 4) {
            int s0 = g_csr_src[beg + p], s1 = g_csr_src[beg + p + 1];
            int s2 = g_csr_src[beg + p + 2], s3 = g_csr_src[beg + p + 3];
            __half2 v0 = *(const __half2*)&g_h[(size_t)s0 * DD + c];
            __half2 v1 = *(const __half2*)&g_h[(size_t)s1 * DD + c];
            __half2 v2 = *(const __half2*)&g_h[(size_t)s2 * DD + c];
            __half2 v3 = *(const __half2*)&g_h[(size_t)s3 * DD + c];
            float w0 = wbuf[p * H + h], w1 = wbuf[(p + 1) * H + h];
            float w2 = wbuf[(p + 2) * H + h], w3 = wbuf[(p + 3) * H + h];
            float2 f0 = __half22float2(v0), f1 = __half22float2(v1);
            float2 f2 = __half22float2(v2), f3 = __half22float2(v3);
            a0 += w0 * f0.x + w1 * f1.x + w2 * f2.x + w3 * f3.x;
            a1 += w0 * f0.y + w1 * f1.y + w2 * f2.y + w3 * f3.y;
        }
        for (; p < deg; p++) {
            int s0 = g_csr_src[beg + p];
            __half2 v0 = *(const __half2*)&g_h[(size_t)s0 * DD + c];
            float w0 = wbuf[p * H + h];
            float2 f0 = __half22float2(v0);
            a0 += w0 * f0.x;
            a1 += w0 * f0.y;
        }
    } else {
        float sdh = sdst[d * H + h];
        float e0 = 0.f;
        for (int p = beg; p < end; p++) {
            int s = g_csr_src[p];
            float tt = ssrc[s * H + h] + sdh;
            tt = tt > 0.f ? tt : 0.2f * tt;
            float w = __expf(tt);
            __half2 v = *(const __half2*)&g_h[(size_t)s * DD + c];
            float2 f = __half22float2(v);
            a0 += w * f.x;
            a1 += w * f.y;
            e0 += w;
        }
        a0 /= (e0 + 1e-16f);
        a1 /= (e0 + 1e-16f);
    }

    if (DO_LN) {
        float v0 = a0 + b[c], v1 = a1 + b[c + 1];
        float s = v0 + v1;
#pragma unroll
        for (int o = 16; o; o >>= 1) s += __shfl_down_sync(0xffffffffu, s, o);
        if ((t & 31) == 0) red[t >> 5] = s;
        __syncthreads();
        float mu =
            (red[0] + red[1] + red[2] + red[3] + red[4] + red[5]) * (1.f / 384.f);
        float dv0 = v0 - mu, dv1 = v1 - mu;
        float d2 = dv0 * dv0 + dv1 * dv1;
#pragma unroll
        for (int o = 16; o; o >>= 1) d2 += __shfl_down_sync(0xffffffffu, d2, o);
        if ((t & 31) == 0) red2[t >> 5] = d2;
        __syncthreads();
        float var =
            (red2[0] + red2[1] + red2[2] + red2[3] + red2[4] + red2[5]) * (1.f / 384.f);
        float rstd = rsqrtf(var + 1e-5f);
        float y0 = dv0 * rstd * gam[c] + bet[c];
        float y1 = dv1 * rstd * gam[c + 1] + bet[c + 1];
        y0 = y0 > 0.f ? tf32f(y0) : 0.f;
        y1 = y1 > 0.f ? tf32f(y1) : 0.f;
        *(float2*)&g_x[(size_t)d * DD + c] = make_float2(y0, y1);
    } else {
        *(float2*)&g_out[(size_t)d * DD + c] = make_float2(a0, a1);
    }
}

// ---------------- batch offsets ----------------
__global__ void offsets_kernel(const int* __restrict__ batch) {
    int g = threadIdx.x;
    if (g > BB) return;
    int lo = 0, hi = NN;
    while (lo < hi) {
        int mid = (lo + hi) >> 1;
        if (batch[mid] < g)
            lo = mid + 1;
        else
            hi = mid;
    }
    g_off[g] = lo;
}

// ---------------- residual + relu(bias) + mean pool (sliced, atomic finish) ----------------
__global__ void pool_kernel(const float* __restrict__ x0, const float* __restrict__ b3,
                            float* __restrict__ out) {
    int g = blockIdx.x, slice = blockIdx.y, c = threadIdx.x;
    int s = g_off[g], e = g_off[g + 1];
    float bias = b3[c], acc = 0.f;
    for (int n = s + slice; n < e; n += 8) {
        float v = g_out[(size_t)n * DD + c] + bias;
        acc += x0[(size_t)n * DD + c] + (v > 0.f ? v : 0.f);
    }
    int cnt = e - s;
    if (cnt < 1) cnt = 1;
    atomicAdd(&out[g * DD + c], acc / (float)cnt);
}

// ---------------- host launch ----------------
extern "C" void kernel_launch(void* const* d_in, const int* in_sizes, int n_in,
                              void* d_out, int out_size) {
    const float* x = (const float*)d_in[0];
    const int* ei = (const int*)d_in[1];
    const int* batch = (const int*)d_in[2];
    const float* W1 = (const float*)d_in[3];
    const float* a1s = (const float*)d_in[4];
    const float* a1d = (const float*)d_in[5];
    const float* b1 = (const float*)d_in[6];
    const float* g1 = (const float*)d_in[7];
    const float* be1 = (const float*)d_in[8];
    const float* W2 = (const float*)d_in[9];
    const float* a2s = (const float*)d_in[10];
    const float* a2d = (const float*)d_in[11];
    const float* b2 = (const float*)d_in[12];
    const float* g2 = (const float*)d_in[13];
    const float* be2 = (const float*)d_in[14];
    const float* W3 = (const float*)d_in[15];
    const float* a3s = (const float*)d_in[16];
    const float* a3d = (const float*)d_in[17];
    const float* b3 = (const float*)d_in[18];
    float* out = (float*)d_out;

    static cudaStream_t aux = nullptr;
    static cudaEvent_t ev0 = nullptr, ev1 = nullptr;
    if (aux == nullptr) {
        cudaStreamCreateWithFlags(&aux, cudaStreamNonBlocking);
        cudaEventCreateWithFlags(&ev0, cudaEventDisableTiming);
        cudaEventCreateWithFlags(&ev1, cudaEventDisableTiming);
    }

    void* pv;
    cudaGetSymbolAddress(&pv, g_deg);
    int* degp = (int*)pv;
    cudaGetSymbolAddress(&pv, g_cur);
    int* curp = (int*)pv;
    cudaGetSymbolAddress(&pv, g_x);
    float* xp = (float*)pv;
    cudaGetSymbolAddress(&pv, g_ssrc);
    float* ssp = (float*)pv;
    cudaGetSymbolAddress(&pv, g_sdst);
    float* sdp = (float*)pv;
    cudaGetSymbolAddress(&pv, g_Wr);
    float* wr = (float*)pv;

    cudaFuncSetAttribute(gemm_mma<4, 96, true>, cudaFuncAttributeMaxDynamicSharedMemorySize,
                         GEMM_SMEM);
    cudaFuncSetAttribute(gemm_mma<4, 96, false>, cudaFuncAttributeMaxDynamicSharedMemorySize,
                         GEMM_SMEM);
    cudaFuncSetAttribute(gemm_mma<6, 64, false>, cudaFuncAttributeMaxDynamicSharedMemorySize,
                         GEMM_SMEM);

    const int* esrc = ei;
    const int* edst = ei + EE;
    int eb = (ETOT + 255) / 256;
    dim3 gemm_grid(3, (NN + 127) / 128);
    const int SLAB = NN * HMAX;

    // ---- fork: CSR build + W2/W3 rounding + offsets + zeroing on aux stream ----
    cudaEventRecord(ev0, 0);
    cudaStreamWaitEvent(aux, ev0, 0);
    cudaMemsetAsync(degp, 0, NN * sizeof(int), aux);
    cudaMemsetAsync(ssp + SLAB, 0, 2 * SLAB * sizeof(float), aux);
    cudaMemsetAsync(sdp + SLAB, 0, 2 * SLAB * sizeof(float), aux);
    round_w23<<<(2 * DD * DD / 4 + 255) / 256, 256, 0, aux>>>(W2, W3);
    count_kernel<<<eb, 256, 0, aux>>>(edst);
    scan_kernel<<<1, 1024, 0, aux>>>();
    cudaMemsetAsync(curp, 0, NN * sizeof(int), aux);
    fill_kernel<<<eb, 256, 0, aux>>>(esrc, edst);
    offsets_kernel<<<1, 128, 0, aux>>>(batch);
    cudaMemsetAsync(out, 0, (size_t)BB * DD * sizeof(float), aux);
    cudaEventRecord(ev1, aux);

    // ---- main stream: W1 rounding + layer-1 logit zeroing (fused) ----
    round_w1<<<(DD * DD / 4 + 255) / 256, 256>>>(W1, ssp, sdp);

    // ---- layer 1 (H=4, C=96) ----
    gemm_mma<4, 96, true><<<gemm_grid, 256, GEMM_SMEM>>>(x, wr, a1s, a1d, ssp, sdp);
    cudaStreamWaitEvent(0, ev1, 0);  // join aux work before aggregation
    agg_kernel<4, 96, true><<<NN, 192>>>(b1, g1, be1, ssp, sdp);

    // ---- layer 2 (H=4, C=96) ----
    gemm_mma<4, 96, false><<<gemm_grid, 256, GEMM_SMEM>>>(xp, wr + DD * DD, a2s, a2d, ssp + SLAB,
                                                          sdp + SLAB);
    agg_kernel<4, 96, true><<<NN, 192>>>(b2, g2, be2, ssp + SLAB, sdp + SLAB);

    // ---- layer 3 (H=6, C=64) ----
    gemm_mma<6, 64, false><<<gemm_grid, 256, GEMM_SMEM>>>(xp, wr + 2 * DD * DD, a3s, a3d,
                                                          ssp + 2 * SLAB, sdp + 2 * SLAB);
    agg_kernel<6, 64, false><<<NN, 192>>>(nullptr, nullptr, nullptr, ssp + 2 * SLAB,
                                          sdp + 2 * SLAB);

    // ---- pooling ----
    pool_kernel<<<dim3(BB, 8), DD>>>(x, b3, out);
}

// round 16
// speedup vs baseline: 1.1212x; 1.1212x over previous
#include <cuda_runtime.h>
#include <cuda_fp16.h>
#include <cstdint>

#define NN 50000
#define EE 500000
#define DD 384
#define BB 64
#define HMAX 6
#define ETOT (EE + NN)
#define MAXDEG 512

// ---------------- scratch (static device allocations) ----------------
__device__ __align__(16) __half g_h[(size_t)NN * DD];   // projected features (fp16)
__device__ __align__(16) float g_out[(size_t)NN * DD];  // layer-3 aggregated output
__device__ __align__(16) float g_x[(size_t)NN * DD];    // layer input (x1, x2), tf32-rounded
__device__ __align__(16) float g_Wr[3 * DD * DD];       // tf32-rounded weights
__device__ float g_ssrc[3 * NN * HMAX];                 // per-layer slabs
__device__ float g_sdst[3 * NN * HMAX];
__device__ int g_deg[NN];
__device__ int g_cur[NN];
__device__ int g_csr_off[NN + 1];
__device__ int g_csr_src[ETOT];
__device__ int g_off[BB + 2];

// ================= helpers =================
__device__ __forceinline__ uint32_t smem_u32(const void* p) {
    uint32_t a;
    asm("{ .reg .u64 t; cvta.to.shared.u64 t, %1; cvt.u32.u64 %0, t; }" : "=r"(a) : "l"(p));
    return a;
}
#define CP16(sa, g) asm volatile("cp.async.cg.shared.global [%0], [%1], 16;" ::"r"(sa), "l"(g))
#define CP_COMMIT() asm volatile("cp.async.commit_group;" ::: "memory")

__device__ __forceinline__ uint32_t to_tf32(float x) {
    uint32_t u;
    asm("cvt.rna.tf32.f32 %0, %1;" : "=r"(u) : "f"(x));
    return u;
}
__device__ __forceinline__ float tf32f(float x) { return __uint_as_float(to_tf32(x)); }

__device__ __forceinline__ void mma_tf32(float* d, uint32_t a0, uint32_t a1, uint32_t a2,
                                         uint32_t a3, uint32_t b0, uint32_t b1) {
    asm volatile(
        "mma.sync.aligned.m16n8k8.row.col.f32.tf32.tf32.f32 "
        "{%0,%1,%2,%3}, {%4,%5,%6,%7}, {%8,%9}, {%0,%1,%2,%3};"
        : "+f"(d[0]), "+f"(d[1]), "+f"(d[2]), "+f"(d[3])
        : "r"(a0), "r"(a1), "r"(a2), "r"(a3), "r"(b0), "r"(b1));
}

// ================= weight pre-round: W1 + layer-1 logit zeroing (critical path) =================
__global__ void round_w1(const float* __restrict__ W1, float* __restrict__ z0,
                         float* __restrict__ z1) {
    int i4 = blockIdx.x * blockDim.x + threadIdx.x;
    const int NW = DD * DD / 4;
    if (i4 < NW) {
        float4 v = ((const float4*)W1)[i4];
        v.x = tf32f(v.x);
        v.y = tf32f(v.y);
        v.z = tf32f(v.z);
        v.w = tf32f(v.w);
        ((float4*)g_Wr)[i4] = v;
    }
    for (int i = i4; i < NN; i += gridDim.x * blockDim.x) {
        ((float4*)z0)[i] = make_float4(0.f, 0.f, 0.f, 0.f);
        ((float4*)z1)[i] = make_float4(0.f, 0.f, 0.f, 0.f);
    }
}

// ================= weight pre-round: W2 + W3 (aux stream) =================
__global__ void round_w23(const float* __restrict__ W2, const float* __restrict__ W3) {
    int i4 = blockIdx.x * blockDim.x + threadIdx.x;
    const int NW = DD * DD / 4;
    if (i4 >= 2 * NW) return;
    const float4* src = (i4 < NW) ? (const float4*)W2 : (const float4*)W3;
    int o = (i4 < NW) ? i4 : i4 - NW;
    float4 v = src[o];
    v.x = tf32f(v.x);
    v.y = tf32f(v.y);
    v.z = tf32f(v.z);
    v.w = tf32f(v.w);
    ((float4*)g_Wr)[NW + i4] = v;
}

// ================= tf32 mma.sync GEMM + fused attention logits =================
#define ST_FLOATS (4608 + 4352)
#define GEMM_SMEM (2 * ST_FLOATS * 4)

template <int H, int C, bool CVTA>
__global__ __launch_bounds__(256, 2) void gemm_mma(const float* __restrict__ A,
                                                   const float* __restrict__ W,
                                                   const float* __restrict__ asrc,
                                                   const float* __restrict__ adst,
                                                   float* __restrict__ ssrc,
                                                   float* __restrict__ sdst) {
    extern __shared__ float sm[];
    int tid = threadIdx.x;
    int m0 = blockIdx.y * 128, n0 = blockIdx.x * 128;
    int lane = tid & 31, wid = tid >> 5;
    int wm = wid & 3, wn = wid >> 2;
    int r = lane >> 2, kq = lane & 3;

    float acc[2][8][4];
#pragma unroll
    for (int i = 0; i < 2; i++)
#pragma unroll
        for (int j = 0; j < 8; j++)
#pragma unroll
            for (int q = 0; q < 4; q++) acc[i][j][q] = 0.f;

    auto issue = [&](int c, int st) {
        float* As = sm + st * ST_FLOATS;
        float* Bs = As + 4608;
        int k0 = c * 32;
#pragma unroll
        for (int i = 0; i < 4; i++) {
            int idx = i * 256 + tid;
            int m = idx >> 3, seg = idx & 7;
            int row = m0 + m;
            if (row > NN - 1) row = NN - 1;
            CP16(smem_u32(As + m * 36 + seg * 4), A + (size_t)row * DD + k0 + seg * 4);
        }
#pragma unroll
        for (int i = 0; i < 4; i++) {
            int idx = i * 256 + tid;
            int kr = idx >> 5, seg = idx & 31;
            CP16(smem_u32(Bs + kr * 136 + seg * 4), W + (size_t)(k0 + kr) * DD + n0 + seg * 4);
        }
        CP_COMMIT();
    };

    issue(0, 0);
    for (int c = 0; c < 12; c++) {
        int st = c & 1;
        if (c < 11) {
            issue(c + 1, st ^ 1);
            asm volatile("cp.async.wait_group 1;" ::: "memory");
        } else {
            asm volatile("cp.async.wait_group 0;" ::: "memory");
        }
        __syncthreads();
        const float* As = sm + st * ST_FLOATS;
        const float* Bs = As + 4608;
#pragma unroll
        for (int ks = 0; ks < 4; ks++) {
            int kk = ks * 8;
            uint32_t a[2][4], b[8][2];
#pragma unroll
            for (int mi = 0; mi < 2; mi++) {
                int row = wm * 32 + mi * 16 + r;
                if (CVTA) {
                    a[mi][0] = to_tf32(As[row * 36 + kk + kq]);
                    a[mi][1] = to_tf32(As[(row + 8) * 36 + kk + kq]);
                    a[mi][2] = to_tf32(As[row * 36 + kk + kq + 4]);
                    a[mi][3] = to_tf32(As[(row + 8) * 36 + kk + kq + 4]);
                } else {
                    a[mi][0] = __float_as_uint(As[row * 36 + kk + kq]);
                    a[mi][1] = __float_as_uint(As[(row + 8) * 36 + kk + kq]);
                    a[mi][2] = __float_as_uint(As[row * 36 + kk + kq + 4]);
                    a[mi][3] = __float_as_uint(As[(row + 8) * 36 + kk + kq + 4]);
                }
            }
#pragma unroll
            for (int j = 0; j < 8; j++) {
                int col = wn * 64 + j * 8 + r;
                b[j][0] = __float_as_uint(Bs[(kk + kq) * 136 + col]);
                b[j][1] = __float_as_uint(Bs[(kk + kq + 4) * 136 + col]);
            }
#pragma unroll
            for (int mi = 0; mi < 2; mi++)
#pragma unroll
                for (int j = 0; j < 8; j++)
                    mma_tf32(acc[mi][j], a[mi][0], a[mi][1], a[mi][2], a[mi][3], b[j][0], b[j][1]);
        }
        __syncthreads();
    }

    // ---- store h as fp16 ----
#pragma unroll
    for (int mi = 0; mi < 2; mi++) {
#pragma unroll
        for (int j = 0; j < 8; j++) {
            int row = m0 + wm * 32 + mi * 16 + r;
            int col = n0 + wn * 64 + j * 8 + kq * 2;
            if (row < NN)
                *(__half2*)&g_h[(size_t)row * DD + col] =
                    __floats2half2_rn(acc[mi][j][0], acc[mi][j][1]);
            if (row + 8 < NN)
                *(__half2*)&g_h[(size_t)(row + 8) * DD + col] =
                    __floats2half2_rn(acc[mi][j][2], acc[mi][j][3]);
        }
    }

    // ---- fused attention logits (fp32 accumulators) ----
    int n0base = n0 + wn * 64;
    int hlo = n0base / C;
    int hhi = (n0base + 63) / C;
    float ss[4][2] = {}, sd[4][2] = {};
#pragma unroll
    for (int j = 0; j < 8; j++) {
        int colb = n0base + j * 8 + kq * 2;
        int bkt = (n0base + j * 8) / C - hlo;
#pragma unroll
        for (int q = 0; q < 2; q++) {
            float as = asrc[colb + q], ad = adst[colb + q];
            ss[0][bkt] += acc[0][j][q] * as;
            sd[0][bkt] += acc[0][j][q] * ad;
            ss[1][bkt] += acc[0][j][2 + q] * as;
            sd[1][bkt] += acc[0][j][2 + q] * ad;
            ss[2][bkt] += acc[1][j][q] * as;
            sd[2][bkt] += acc[1][j][q] * ad;
            ss[3][bkt] += acc[1][j][2 + q] * as;
            sd[3][bkt] += acc[1][j][2 + q] * ad;
        }
    }
#pragma unroll
    for (int i = 0; i < 4; i++)
#pragma unroll
        for (int bkt = 0; bkt < 2; bkt++)
#pragma unroll
            for (int o = 1; o < 4; o <<= 1) {
                ss[i][bkt] += __shfl_xor_sync(0xffffffffu, ss[i][bkt], o);
                sd[i][bkt] += __shfl_xor_sync(0xffffffffu, sd[i][bkt], o);
            }
    if (kq == 0) {
        int rows[4] = {m0 + wm * 32 + r, m0 + wm * 32 + r + 8, m0 + wm * 32 + r + 16,
                       m0 + wm * 32 + r + 24};
#pragma unroll
        for (int i = 0; i < 4; i++) {
            if (rows[i] < NN) {
                atomicAdd(&ssrc[rows[i] * H + hlo], ss[i][0]);
                atomicAdd(&sdst[rows[i] * H + hlo], sd[i][0]);
                if (hhi > hlo) {
                    atomicAdd(&ssrc[rows[i] * H + hlo + 1], ss[i][1]);
                    atomicAdd(&sdst[rows[i] * H + hlo + 1], sd[i][1]);
                }
            }
        }
    }
}

// ---------------- CSR build ----------------
__global__ void count_kernel(const int* __restrict__ edst) {
    int e = blockIdx.x * blockDim.x + threadIdx.x;
    if (e >= ETOT) return;
    int d = (e < EE) ? edst[e] : (e - EE);
    atomicAdd(&g_deg[d], 1);
}

__global__ void scan_kernel() {
    const int T = 1024;
    const int CH = (NN + T - 1) / T;
    __shared__ int warp_sums[32];
    int t = threadIdx.x;
    int base = t * CH;
    int s = 0;
    for (int i = 0; i < CH; i++) {
        int idx = base + i;
        if (idx < NN) s += g_deg[idx];
    }
    int lane = t & 31, wid = t >> 5;
    int v = s;
#pragma unroll
    for (int o = 1; o < 32; o <<= 1) {
        int u = __shfl_up_sync(0xffffffffu, v, o);
        if (lane >= o) v += u;
    }
    if (lane == 31) warp_sums[wid] = v;
    __syncthreads();
    if (wid == 0) {
        int w = warp_sums[lane];
#pragma unroll
        for (int o = 1; o < 32; o <<= 1) {
            int u = __shfl_up_sync(0xffffffffu, w, o);
            if (lane >= o) w += u;
        }
        warp_sums[lane] = w;
    }
    __syncthreads();
    int excl = v - s + (wid > 0 ? warp_sums[wid - 1] : 0);
    int run = excl;
    for (int i = 0; i < CH; i++) {
        int idx = base + i;
        if (idx < NN) {
            g_csr_off[idx] = run;
            run += g_deg[idx];
        }
    }
    if (t == 0) g_csr_off[NN] = ETOT;
}

__global__ void fill_kernel(const int* __restrict__ esrc, const int* __restrict__ edst) {
    int e = blockIdx.x * blockDim.x + threadIdx.x;
    if (e >= ETOT) return;
    int s, d;
    if (e < EE) {
        s = esrc[e];
        d = edst[e];
    } else {
        s = d = e - EE;
    }
    int slot = g_csr_off[d] + atomicAdd(&g_cur[d], 1);
    g_csr_src[slot] = s;
}

// ---------------- fused softmax-alpha + gather + (bias+LN+ReLU) ----------------
// 128 threads, 3 channels/thread, srcs staged in smem, gather unrolled x8 (24 LDG in flight).
template <int H, int C, bool DO_LN>
__global__ __launch_bounds__(128) void agg_kernel(const float* __restrict__ b,
                                                  const float* __restrict__ gam,
                                                  const float* __restrict__ bet,
                                                  const float* __restrict__ ssrc,
                                                  const float* __restrict__ sdst) {
    __shared__ float wbuf[MAXDEG * H];
    __shared__ int sbuf[MAXDEG];
    __shared__ float invd[H];
    __shared__ float red[4], red2[4];
    int d = blockIdx.x;
    int t = threadIdx.x;
    int beg = g_csr_off[d], end = g_csr_off[d + 1];
    int deg = end - beg;
    const int c0 = t, c1 = t + 128, c2 = t + 256;
    const int h0 = c0 / C, h1 = c1 / C, h2 = c2 / C;
    float n0 = 0.f, n1 = 0.f, n2 = 0.f;

    if (deg <= MAXDEG) {
        for (int i = t; i < deg; i += 128) sbuf[i] = g_csr_src[beg + i];
        __syncthreads();
        int items = deg * H;
        for (int i = t; i < items; i += 128) {
            int p = i / H, h = i - p * H;
            int s = sbuf[p];
            float tt = ssrc[s * H + h] + sdst[d * H + h];
            tt = tt > 0.f ? tt : 0.2f * tt;
            wbuf[i] = __expf(tt);
        }
        __syncthreads();
        if (t < H) {
            float dn = 0.f;
            for (int p = 0; p < deg; p++) dn += wbuf[p * H + t];
            invd[t] = 1.f / (dn + 1e-16f);
        }
        __syncthreads();
        for (int i = t; i < items; i += 128) {
            int h = i - (i / H) * H;
            wbuf[i] *= invd[h];
        }
        __syncthreads();
        int p = 0;
        for (; p + 8 <= deg; p += 8) {
            int sidx[8];
#pragma unroll
            for (int q = 0; q < 8; q++) sidx[q] = sbuf[p + q];
            float v0[8], v1[8], v2[8];
#pragma unroll
            for (int q = 0; q < 8; q++) {
                const __half* hr = g_h + (size_t)sidx[q] * DD;
                v0[q] = __half2float(hr[c0]);
                v1[q] = __half2float(hr[c1]);
                v2[q] = __half2float(hr[c2]);
            }
#pragma unroll
            for (int q = 0; q < 8; q++) {
                n0 += wbuf[(p + q) * H + h0] * v0[q];
                n1 += wbuf[(p + q) * H + h1] * v1[q];
                n2 += wbuf[(p + q) * H + h2] * v2[q];
            }
        }
        for (; p < deg; p++) {
            const __half* hr = g_h + (size_t)sbuf[p] * DD;
            n0 += wbuf[p * H + h0] * __half2float(hr[c0]);
            n1 += wbuf[p * H + h1] * __half2float(hr[c1]);
            n2 += wbuf[p * H + h2] * __half2float(hr[c2]);
        }
    } else {
        float sd0 = sdst[d * H + h0], sd1 = sdst[d * H + h1], sd2 = sdst[d * H + h2];
        float e0 = 0.f, e1 = 0.f, e2 = 0.f;
        for (int p = beg; p < end; p++) {
            int s = g_csr_src[p];
            const __half* hr = g_h + (size_t)s * DD;
            float t0 = ssrc[s * H + h0] + sd0;
            float t1 = ssrc[s * H + h1] + sd1;
            float t2 = ssrc[s * H + h2] + sd2;
            t0 = t0 > 0.f ? t0 : 0.2f * t0;
            t1 = t1 > 0.f ? t1 : 0.2f * t1;
            t2 = t2 > 0.f ? t2 : 0.2f * t2;
            float w0 = __expf(t0), w1 = __expf(t1), w2 = __expf(t2);
            n0 += w0 * __half2float(hr[c0]);
            n1 += w1 * __half2float(hr[c1]);
            n2 += w2 * __half2float(hr[c2]);
            e0 += w0;
            e1 += w1;
            e2 += w2;
        }
        n0 /= (e0 + 1e-16f);
        n1 /= (e1 + 1e-16f);
        n2 /= (e2 + 1e-16f);
    }

    if (DO_LN) {
        float v0 = n0 + b[c0], v1 = n1 + b[c1], v2 = n2 + b[c2];
        float s = v0 + v1 + v2;
#pragma unroll
        for (int o = 16; o; o >>= 1) s += __shfl_down_sync(0xffffffffu, s, o);
        if ((t & 31) == 0) red[t >> 5] = s;
        __syncthreads();
        float mu = (red[0] + red[1] + red[2] + red[3]) * (1.f / 384.f);
        float dv0 = v0 - mu, dv1 = v1 - mu, dv2 = v2 - mu;
        float d2 = dv0 * dv0 + dv1 * dv1 + dv2 * dv2;
#pragma unroll
        for (int o = 16; o; o >>= 1) d2 += __shfl_down_sync(0xffffffffu, d2, o);
        if ((t & 31) == 0) red2[t >> 5] = d2;
        __syncthreads();
        float var = (red2[0] + red2[1] + red2[2] + red2[3]) * (1.f / 384.f);
        float rstd = rsqrtf(var + 1e-5f);
        float y0 = dv0 * rstd * gam[c0] + bet[c0];
        float y1 = dv1 * rstd * gam[c1] + bet[c1];
        float y2 = dv2 * rstd * gam[c2] + bet[c2];
        float* o = g_x + (size_t)d * DD;
        o[c0] = y0 > 0.f ? tf32f(y0) : 0.f;
        o[c1] = y1 > 0.f ? tf32f(y1) : 0.f;
        o[c2] = y2 > 0.f ? tf32f(y2) : 0.f;
    } else {
        float* o = g_out + (size_t)d * DD;
        o[c0] = n0;
        o[c1] = n1;
        o[c2] = n2;
    }
}

// ---------------- batch offsets ----------------
__global__ void offsets_kernel(const int* __restrict__ batch) {
    int g = threadIdx.x;
    if (g > BB) return;
    int lo = 0, hi = NN;
    while (lo < hi) {
        int mid = (lo + hi) >> 1;
        if (batch[mid] < g)
            lo = mid + 1;
        else
            hi = mid;
    }
    g_off[g] = lo;
}

// ---------------- residual + relu(bias) + mean pool (sliced, atomic finish) ----------------
__global__ void pool_kernel(const float* __restrict__ x0, const float* __restrict__ b3,
                            float* __restrict__ out) {
    int g = blockIdx.x, slice = blockIdx.y, c = threadIdx.x;
    int s = g_off[g], e = g_off[g + 1];
    float bias = b3[c], acc = 0.f;
    for (int n = s + slice; n < e; n += 8) {
        float v = g_out[(size_t)n * DD + c] + bias;
        acc += x0[(size_t)n * DD + c] + (v > 0.f ? v : 0.f);
    }
    int cnt = e - s;
    if (cnt < 1) cnt = 1;
    atomicAdd(&out[g * DD + c], acc / (float)cnt);
}

// ---------------- host launch ----------------
extern "C" void kernel_launch(void* const* d_in, const int* in_sizes, int n_in,
                              void* d_out, int out_size) {
    const float* x = (const float*)d_in[0];
    const int* ei = (const int*)d_in[1];
    const int* batch = (const int*)d_in[2];
    const float* W1 = (const float*)d_in[3];
    const float* a1s = (const float*)d_in[4];
    const float* a1d = (const float*)d_in[5];
    const float* b1 = (const float*)d_in[6];
    const float* g1 = (const float*)d_in[7];
    const float* be1 = (const float*)d_in[8];
    const float* W2 = (const float*)d_in[9];
    const float* a2s = (const float*)d_in[10];
    const float* a2d = (const float*)d_in[11];
    const float* b2 = (const float*)d_in[12];
    const float* g2 = (const float*)d_in[13];
    const float* be2 = (const float*)d_in[14];
    const float* W3 = (const float*)d_in[15];
    const float* a3s = (const float*)d_in[16];
    const float* a3d = (const float*)d_in[17];
    const float* b3 = (const float*)d_in[18];
    float* out = (float*)d_out;

    static cudaStream_t aux = nullptr;
    static cudaEvent_t ev0 = nullptr, ev1 = nullptr;
    if (aux == nullptr) {
        cudaStreamCreateWithFlags(&aux, cudaStreamNonBlocking);
        cudaEventCreateWithFlags(&ev0, cudaEventDisableTiming);
        cudaEventCreateWithFlags(&ev1, cudaEventDisableTiming);
    }

    void* pv;
    cudaGetSymbolAddress(&pv, g_deg);
    int* degp = (int*)pv;
    cudaGetSymbolAddress(&pv, g_cur);
    int* curp = (int*)pv;
    cudaGetSymbolAddress(&pv, g_x);
    float* xp = (float*)pv;
    cudaGetSymbolAddress(&pv, g_ssrc);
    float* ssp = (float*)pv;
    cudaGetSymbolAddress(&pv, g_sdst);
    float* sdp = (float*)pv;
    cudaGetSymbolAddress(&pv, g_Wr);
    float* wr = (float*)pv;

    cudaFuncSetAttribute(gemm_mma<4, 96, true>, cudaFuncAttributeMaxDynamicSharedMemorySize,
                         GEMM_SMEM);
    cudaFuncSetAttribute(gemm_mma<4, 96, false>, cudaFuncAttributeMaxDynamicSharedMemorySize,
                         GEMM_SMEM);
    cudaFuncSetAttribute(gemm_mma<6, 64, false>, cudaFuncAttributeMaxDynamicSharedMemorySize,
                         GEMM_SMEM);

    const int* esrc = ei;
    const int* edst = ei + EE;
    int eb = (ETOT + 255) / 256;
    dim3 gemm_grid(3, (NN + 127) / 128);
    const int SLAB = NN * HMAX;

    // ---- fork: CSR build + W2/W3 rounding + offsets + zeroing on aux stream ----
    cudaEventRecord(ev0, 0);
    cudaStreamWaitEvent(aux, ev0, 0);
    cudaMemsetAsync(degp, 0, NN * sizeof(int), aux);
    cudaMemsetAsync(ssp + SLAB, 0, 2 * SLAB * sizeof(float), aux);
    cudaMemsetAsync(sdp + SLAB, 0, 2 * SLAB * sizeof(float), aux);
    round_w23<<<(2 * DD * DD / 4 + 255) / 256, 256, 0, aux>>>(W2, W3);
    count_kernel<<<eb, 256, 0, aux>>>(edst);
    scan_kernel<<<1, 1024, 0, aux>>>();
    cudaMemsetAsync(curp, 0, NN * sizeof(int), aux);
    fill_kernel<<<eb, 256, 0, aux>>>(esrc, edst);
    offsets_kernel<<<1, 128, 0, aux>>>(batch);
    cudaMemsetAsync(out, 0, (size_t)BB * DD * sizeof(float), aux);
    cudaEventRecord(ev1, aux);

    // ---- main stream: W1 rounding + layer-1 logit zeroing (fused) ----
    round_w1<<<(DD * DD / 4 + 255) / 256, 256>>>(W1, ssp, sdp);

    // ---- layer 1 (H=4, C=96) ----
    gemm_mma<4, 96, true><<<gemm_grid, 256, GEMM_SMEM>>>(x, wr, a1s, a1d, ssp, sdp);
    cudaStreamWaitEvent(0, ev1, 0);  // join aux work before aggregation
    agg_kernel<4, 96, true><<<NN, 128>>>(b1, g1, be1, ssp, sdp);

    // ---- layer 2 (H=4, C=96) ----
    gemm_mma<4, 96, false><<<gemm_grid, 256, GEMM_SMEM>>>(xp, wr + DD * DD, a2s, a2d, ssp + SLAB,
                                                          sdp + SLAB);
    agg_kernel<4, 96, true><<<NN, 128>>>(b2, g2, be2, ssp + SLAB, sdp + SLAB);

    // ---- layer 3 (H=6, C=64) ----
    gemm_mma<6, 64, false><<<gemm_grid, 256, GEMM_SMEM>>>(xp, wr + 2 * DD * DD, a3s, a3d,
                                                          ssp + 2 * SLAB, sdp + 2 * SLAB);
    agg_kernel<6, 64, false><<<NN, 128>>>(nullptr, nullptr, nullptr, ssp + 2 * SLAB,
                                          sdp + 2 * SLAB);

    // ---- pooling ----
    pool_kernel<<<dim3(BB, 8), DD>>>(x, b3, out);
}